// round 4
// baseline (speedup 1.0000x reference)
#include <cuda_runtime.h>
#include <cuda_bf16.h>
#include <cstdint>

// GAT head. Attention GEMM via mma.sync bf16 (3-pass hi/lo split, fp32 acc).
// R4: (a) MMA issue reordered pass-outer so same-accumulator MMAs are spaced
//     by 8 independent ones (R3 chained them -> issue stuck at 33%);
//     (b) front-end fused into one kernel (h never hits gmem as fp32).

#define NN     8192
#define INF    256
#define OUTF   64
#define ALPHA  0.2f

#define JSPLIT 2
#define BI     128
#define BJ     64
#define NTILES ((NN / JSPLIT) / BJ)   // 64

// ---- scratch ----
__device__ float g_s1[NN];
__device__ float g_s2[NN];
__device__ uint4 g_hThi4[OUTF * NN / 8];   // hT hi bf16, [64 c][1024 uint4]
__device__ uint4 g_hTlo4[OUTF * NN / 8];   // hT lo bf16
__device__ float g_acc[JSPLIT * NN * OUTF];
__device__ float g_z  [JSPLIT * NN];

// ---- dynamic smem layout for k_attn ----
#define ADJ_PITCH 288                       // 64 ints + 32B pad
#define OFF_S1    0
#define OFF_ADJ0  1024
#define OFF_ADJ1  (OFF_ADJ0 + BI * ADJ_PITCH)
#define OFF_HHI0  (OFF_ADJ1 + BI * ADJ_PITCH)
#define OFF_HLO0  (OFF_HHI0 + 8192)
#define OFF_HHI1  (OFF_HLO0 + 8192)
#define OFF_HLO1  (OFF_HHI1 + 8192)
#define SMEM_ATTN (OFF_HLO1 + 8192)         // 107520
#define SMEM_FRONT 65536                    // X tile / h tile (aliased)

__device__ __forceinline__ uint32_t smem_u32(const void* p) {
    uint32_t a;
    asm("{ .reg .u64 t; cvta.to.shared.u64 t, %1; cvt.u32.u64 %0, t; }" : "=r"(a) : "l"(p));
    return a;
}
__device__ __forceinline__ void cpa16(uint32_t dst, const void* src) {
    asm volatile("cp.async.ca.shared.global [%0], [%1], 16;" :: "r"(dst), "l"(src));
}
__device__ __forceinline__ void ldsm4(uint32_t* r, uint32_t addr) {
    asm volatile("ldmatrix.sync.aligned.m8n8.x4.shared.b16 {%0,%1,%2,%3}, [%4];"
                 : "=r"(r[0]), "=r"(r[1]), "=r"(r[2]), "=r"(r[3]) : "r"(addr));
}
__device__ __forceinline__ void mma_bf16(float* c, uint32_t a0, uint32_t a1,
                                         uint32_t a2, uint32_t a3,
                                         uint32_t b0, uint32_t b1) {
    asm volatile("mma.sync.aligned.m16n8k16.row.col.f32.bf16.bf16.f32 "
                 "{%0,%1,%2,%3}, {%4,%5,%6,%7}, {%8,%9}, {%0,%1,%2,%3};"
                 : "+f"(c[0]), "+f"(c[1]), "+f"(c[2]), "+f"(c[3])
                 : "r"(a0), "r"(a1), "r"(a2), "r"(a3), "r"(b0), "r"(b1));
}
__device__ __forceinline__ uint32_t pack_bf16x2(float lo, float hi) {
    uint32_t r;  // lo lands in low 16 bits
    asm("cvt.rn.bf16x2.f32 %0, %1, %2;" : "=r"(r) : "f"(hi), "f"(lo));
    return r;
}
__device__ __forceinline__ uint32_t lo_pack(uint32_t hi, float w0, float w1) {
    const float h0 = __uint_as_float(hi << 16);
    const float h1 = __uint_as_float(hi & 0xffff0000u);
    return pack_bf16x2(w0 - h0, w1 - h1);
}
__device__ __forceinline__ float wval(float x, int m) {
    const float lr = fmaxf(x, ALPHA * x);
    const float v  = __expf(lr);
    return (m > 0) ? v : 0.f;
}

// ---------------------------------------------------------------------------
// Kernel 1 (fused front): h = X@W for 64 rows; s1/s2; bf16 hi/lo split +
// transpose to g_hThi4/g_hTlo4. h never goes to gmem in fp32.
// ---------------------------------------------------------------------------
__global__ __launch_bounds__(256, 1) void k_front(const float* __restrict__ X,
                                                  const float* __restrict__ W,
                                                  const float* __restrict__ a1,
                                                  const float* __restrict__ a2) {
    extern __shared__ float fsm[];     // 64 KB: X tile [64][256], later h [64][65]
    const int tid = threadIdx.x;
    const int r0  = blockIdx.x * 64;

    // stage X tile [64][256]
    const float4* Xg  = (const float4*)(X + (long)r0 * INF);
    float4*       Xs4 = (float4*)fsm;
#pragma unroll
    for (int it = 0; it < 16; it++) Xs4[it * 256 + tid] = Xg[it * 256 + tid];
    __syncthreads();

    // h: thread = (rr0 = tid>>4 plus 4 strided sub-rows, 4 cols tc*4..)
    const int tc  = tid & 15;
    const int rr0 = tid >> 4;
    float4 acc[4];
#pragma unroll
    for (int s = 0; s < 4; s++) acc[s] = make_float4(0.f, 0.f, 0.f, 0.f);
    const float4* W4 = (const float4*)W;
    for (int k = 0; k < INF; k++) {
        const float4 w = __ldg(&W4[k * 16 + tc]);
#pragma unroll
        for (int s = 0; s < 4; s++) {
            const float x = fsm[(rr0 + s * 16) * 256 + k];
            acc[s].x += x * w.x; acc[s].y += x * w.y;
            acc[s].z += x * w.z; acc[s].w += x * w.w;
        }
    }
    __syncthreads();   // all X reads done; reuse fsm as h [64][65]

#pragma unroll
    for (int s = 0; s < 4; s++) {
        const int row = rr0 + s * 16;
        fsm[row * 65 + tc * 4 + 0] = acc[s].x;
        fsm[row * 65 + tc * 4 + 1] = acc[s].y;
        fsm[row * 65 + tc * 4 + 2] = acc[s].z;
        fsm[row * 65 + tc * 4 + 3] = acc[s].w;
    }
    __syncthreads();

    // s1/s2 for 64 rows (threads 0..63)
    if (tid < 64) {
        float p1 = 0.f, p2 = 0.f;
#pragma unroll 8
        for (int c = 0; c < OUTF; c++) {
            const float hv = fsm[tid * 65 + c];
            p1 += hv * __ldg(&a1[c]);
            p2 += hv * __ldg(&a2[c]);
        }
        g_s1[r0 + tid] = p1;
        g_s2[r0 + tid] = p2;
    }

    // transpose + hi/lo split: thread = (c = tid>>2, seg = tid&3 -> 16 j's)
    const int c = tid >> 2, seg = tid & 3;
    float v[16];
#pragma unroll
    for (int k = 0; k < 16; k++) v[k] = fsm[(seg * 16 + k) * 65 + c];
    uint32_t uh[8], ul[8];
#pragma unroll
    for (int p = 0; p < 8; p++) {
        const float f0 = v[2 * p], f1 = v[2 * p + 1];
        uh[p] = pack_bf16x2(f0, f1);
        ul[p] = lo_pack(uh[p], f0, f1);
    }
    const int base = c * 1024 + (r0 >> 3) + seg * 2;
    g_hThi4[base]     = make_uint4(uh[0], uh[1], uh[2], uh[3]);
    g_hThi4[base + 1] = make_uint4(uh[4], uh[5], uh[6], uh[7]);
    g_hTlo4[base]     = make_uint4(ul[0], ul[1], ul[2], ul[3]);
    g_hTlo4[base + 1] = make_uint4(ul[4], ul[5], ul[6], ul[7]);
}

// ---------------------------------------------------------------------------
// Kernel 2: fused masked-exp weight-gen + mma.sync 3xBF16 GEMM.
// ---------------------------------------------------------------------------
__device__ __forceinline__ void stage_tile(uint32_t sb, int buf, const int* __restrict__ adj,
                                           int ibase, int j0, int tid) {
    const uint32_t adjB = sb + (buf ? OFF_ADJ1 : OFF_ADJ0);
#pragma unroll
    for (int it = 0; it < 8; it++) {
        const int lin = it * 256 + tid;
        const int ii = lin >> 4, ch = lin & 15;
        cpa16(adjB + ii * ADJ_PITCH + ch * 16,
              adj + (long)(ibase + ii) * NN + j0 + ch * 4);
    }
    const uint32_t hhiB = sb + (buf ? OFF_HHI1 : OFF_HHI0);
    const uint32_t hloB = sb + (buf ? OFF_HLO1 : OFF_HLO0);
#pragma unroll
    for (int it = 0; it < 2; it++) {
        const int lin = it * 256 + tid;
        const int n = lin >> 3, ch = lin & 7;
        const uint32_t off = n * 128 + ((ch ^ (n & 7)) << 4);
        cpa16(hhiB + off, g_hThi4 + n * 1024 + (j0 >> 3) + ch);
        cpa16(hloB + off, g_hTlo4 + n * 1024 + (j0 >> 3) + ch);
    }
}

__global__ __launch_bounds__(256, 1) void k_attn(const int* __restrict__ adj) {
    extern __shared__ __align__(128) unsigned char smem[];
    const uint32_t sb = smem_u32(smem);
    const int tid = threadIdx.x, lane = tid & 31, wid = tid >> 5;
    const int ibase  = blockIdx.x * BI;
    const int jsplit = blockIdx.y;
    const int jbase  = jsplit * (NN / JSPLIT);

    if (tid < BI) ((float*)smem)[tid] = g_s1[ibase + tid];

    const int g  = lane >> 2;
    const int t2 = (lane & 3) * 2;
    const int p_nloc = ((lane >> 4) << 3) + (lane & 7);
    const int ckb    = (lane >> 3) & 1;

    float acc[8][4];
#pragma unroll
    for (int n = 0; n < 8; n++)
#pragma unroll
        for (int q = 0; q < 4; q++) acc[n][q] = 0.f;
    float z0 = 0.f, z1 = 0.f;

    stage_tile(sb, 0, adj, ibase, jbase, tid);
    asm volatile("cp.async.commit_group;" ::: "memory");

    const int r0loc = wid * 16 + g;
    const int r1loc = r0loc + 8;

    for (int t = 0; t < NTILES; t++) {
        const int b  = t & 1;
        const int j0 = jbase + t * BJ;

        if (t + 1 < NTILES) {
            stage_tile(sb, b ^ 1, adj, ibase, j0 + BJ, tid);
            asm volatile("cp.async.commit_group;" ::: "memory");
            asm volatile("cp.async.wait_group 1;" ::: "memory");
        } else {
            asm volatile("cp.async.wait_group 0;" ::: "memory");
        }
        __syncthreads();

        const uint32_t adjOff = b ? OFF_ADJ1 : OFF_ADJ0;
        const uint32_t hhiB = sb + (b ? OFF_HHI1 : OFF_HHI0);
        const uint32_t hloB = sb + (b ? OFF_HLO1 : OFF_HLO0);
        const float s1r0 = ((const float*)smem)[r0loc];
        const float s1r1 = ((const float*)smem)[r1loc];

#pragma unroll
        for (int ks = 0; ks < 4; ks++) {
            const int jk = j0 + ks * 16;

            // ---- B fragments ----
            uint32_t bh[4][4], bl[4][4];
            const int ck = ks * 2 + ckb;
#pragma unroll
            for (int p = 0; p < 4; p++) {
                const int nl = p * 16 + p_nloc;
                const uint32_t off = nl * 128 + ((ck ^ (nl & 7)) << 4);
                ldsm4(bh[p], hhiB + off);
                ldsm4(bl[p], hloB + off);
            }

            // ---- A fragments: masked-exp weights ----
            const unsigned char* aR0 = smem + adjOff + r0loc * ADJ_PITCH + (ks * 16 + t2) * 4;
            const unsigned char* aR1 = smem + adjOff + r1loc * ADJ_PITCH + (ks * 16 + t2) * 4;
            const int2 m00 = *(const int2*)aR0;
            const int2 m01 = *(const int2*)(aR0 + 32);
            const int2 m10 = *(const int2*)aR1;
            const int2 m11 = *(const int2*)(aR1 + 32);
            const float2 sa  = *(const float2*)&g_s2[jk + t2];
            const float2 sb2 = *(const float2*)&g_s2[jk + t2 + 8];

            const float w00 = wval(s1r0 + sa.x,  m00.x), w01 = wval(s1r0 + sa.y,  m00.y);
            const float w02 = wval(s1r0 + sb2.x, m01.x), w03 = wval(s1r0 + sb2.y, m01.y);
            const float w10 = wval(s1r1 + sa.x,  m10.x), w11 = wval(s1r1 + sa.y,  m10.y);
            const float w12 = wval(s1r1 + sb2.x, m11.x), w13 = wval(s1r1 + sb2.y, m11.y);
            z0 += (w00 + w01) + (w02 + w03);
            z1 += (w10 + w11) + (w12 + w13);

            const uint32_t a0h = pack_bf16x2(w00, w01), a1h = pack_bf16x2(w10, w11);
            const uint32_t a2h = pack_bf16x2(w02, w03), a3h = pack_bf16x2(w12, w13);
            const uint32_t a0l = lo_pack(a0h, w00, w01), a1l = lo_pack(a1h, w10, w11);
            const uint32_t a2l = lo_pack(a2h, w02, w03), a3l = lo_pack(a3h, w12, w13);

            // ---- 24 mma, PASS-OUTER: same-acc MMAs spaced by 8 indep issues
            // pass 0: A_hi x B_hi
#pragma unroll
            for (int p = 0; p < 4; p++)
#pragma unroll
                for (int q = 0; q < 2; q++)
                    mma_bf16(acc[p * 2 + q], a0h, a1h, a2h, a3h,
                             bh[p][q * 2], bh[p][q * 2 + 1]);
            // pass 1: A_lo x B_hi
#pragma unroll
            for (int p = 0; p < 4; p++)
#pragma unroll
                for (int q = 0; q < 2; q++)
                    mma_bf16(acc[p * 2 + q], a0l, a1l, a2l, a3l,
                             bh[p][q * 2], bh[p][q * 2 + 1]);
            // pass 2: A_hi x B_lo
#pragma unroll
            for (int p = 0; p < 4; p++)
#pragma unroll
                for (int q = 0; q < 2; q++)
                    mma_bf16(acc[p * 2 + q], a0h, a1h, a2h, a3h,
                             bl[p][q * 2], bl[p][q * 2 + 1]);
        }
        __syncthreads();
    }

    // ---- Z: quad reduction ----
    z0 += __shfl_xor_sync(0xffffffffu, z0, 1);
    z0 += __shfl_xor_sync(0xffffffffu, z0, 2);
    z1 += __shfl_xor_sync(0xffffffffu, z1, 1);
    z1 += __shfl_xor_sync(0xffffffffu, z1, 2);
    if ((lane & 3) == 0) {
        g_z[(long)jsplit * NN + ibase + r0loc] = z0;
        g_z[(long)jsplit * NN + ibase + r1loc] = z1;
    }

    // ---- partial numerators ----
    const long obase = (long)jsplit * NN + ibase;
#pragma unroll
    for (int nt = 0; nt < 8; nt++) {
        const int col = nt * 8 + t2;
        *(float2*)&g_acc[(obase + r0loc) * OUTF + col] = make_float2(acc[nt][0], acc[nt][1]);
        *(float2*)&g_acc[(obase + r1loc) * OUTF + col] = make_float2(acc[nt][2], acc[nt][3]);
    }
}

// ---------------------------------------------------------------------------
// Kernel 3: combine splits, normalize, ELU.
// ---------------------------------------------------------------------------
__global__ __launch_bounds__(256) void k_combine(float* __restrict__ out) {
    const int idx = blockIdx.x * 256 + threadIdx.x;
    const int row = idx >> 6;
    float z = 0.f, v = 0.f;
#pragma unroll
    for (int s = 0; s < JSPLIT; s++) {
        z += g_z[(long)s * NN + row];
        v += g_acc[(long)s * NN * OUTF + idx];
    }
    v /= z;
    out[idx] = (v > 0.f) ? v : expm1f(v);
}

// ---------------------------------------------------------------------------
extern "C" void kernel_launch(void* const* d_in, const int* in_sizes, int n_in,
                              void* d_out, int out_size) {
    (void)in_sizes; (void)n_in; (void)out_size;
    const float* X   = (const float*)d_in[0];
    const int*   adj = (const int*)  d_in[1];
    const float* W   = (const float*)d_in[2];
    const float* a1  = (const float*)d_in[3];
    const float* a2  = (const float*)d_in[4];
    float* out = (float*)d_out;

    cudaFuncSetAttribute(k_front, cudaFuncAttributeMaxDynamicSharedMemorySize, SMEM_FRONT);
    cudaFuncSetAttribute(k_attn,  cudaFuncAttributeMaxDynamicSharedMemorySize, SMEM_ATTN);

    k_front  <<<NN / 64, 256, SMEM_FRONT>>>(X, W, a1, a2);
    k_attn   <<<dim3(NN / BI, JSPLIT), 256, SMEM_ATTN>>>(adj);
    k_combine<<<NN * OUTF / 256, 256>>>(out);
}

// round 6
// speedup vs baseline: 1.0966x; 1.0966x over previous
#include <cuda_runtime.h>
#include <cuda_bf16.h>
#include <cstdint>

// GAT head. Attention GEMM via mma.sync bf16 (3-pass hi/lo split, fp32 acc).
// R5 (resubmit after infra failure): k_attn at 512 threads (4 warps/SMSP,
// ks-loop split across warp halves, register accumulators merged via one
// end-of-kernel smem reduction); front end re-fused at 8 rows/CTA.

#define NN     8192
#define INF    256
#define OUTF   64
#define ALPHA  0.2f

#define JSPLIT 2
#define BI     128
#define BJ     64
#define NTILES ((NN / JSPLIT) / BJ)   // 64

// ---- scratch ----
__device__ float g_s1[NN];
__device__ float g_s2[NN];
__device__ uint4 g_hThi4[OUTF * NN / 8];   // hT hi bf16, [64 c][1024 uint4]
__device__ uint4 g_hTlo4[OUTF * NN / 8];   // hT lo bf16
__device__ float g_acc[JSPLIT * NN * OUTF];
__device__ float g_z  [JSPLIT * NN];

// ---- dynamic smem layout for k_attn ----
#define ADJ_PITCH 288                       // 64 ints + 32B pad
#define OFF_S1    0
#define OFF_ADJ0  1024
#define OFF_ADJ1  (OFF_ADJ0 + BI * ADJ_PITCH)
#define OFF_HHI0  (OFF_ADJ1 + BI * ADJ_PITCH)
#define OFF_HLO0  (OFF_HHI0 + 8192)
#define OFF_HHI1  (OFF_HLO0 + 8192)
#define OFF_HLO1  (OFF_HHI1 + 8192)
#define SMEM_ATTN (OFF_HLO1 + 8192)         // 107520
// end-of-kernel reduction buffers alias the (dead) adj double buffer
#define OFF_RED   OFF_ADJ0                  // 256 slots x 36 floats = 36864 B
#define OFF_ZRED  OFF_ADJ1                  // 128 floats
#define RED_STRIDE 36                       // floats; conflict-free phases

__device__ __forceinline__ uint32_t smem_u32(const void* p) {
    uint32_t a;
    asm("{ .reg .u64 t; cvta.to.shared.u64 t, %1; cvt.u32.u64 %0, t; }" : "=r"(a) : "l"(p));
    return a;
}
__device__ __forceinline__ void cpa16(uint32_t dst, const void* src) {
    asm volatile("cp.async.ca.shared.global [%0], [%1], 16;" :: "r"(dst), "l"(src));
}
__device__ __forceinline__ void ldsm4(uint32_t* r, uint32_t addr) {
    asm volatile("ldmatrix.sync.aligned.m8n8.x4.shared.b16 {%0,%1,%2,%3}, [%4];"
                 : "=r"(r[0]), "=r"(r[1]), "=r"(r[2]), "=r"(r[3]) : "r"(addr));
}
__device__ __forceinline__ void mma_bf16(float* c, uint32_t a0, uint32_t a1,
                                         uint32_t a2, uint32_t a3,
                                         uint32_t b0, uint32_t b1) {
    asm volatile("mma.sync.aligned.m16n8k16.row.col.f32.bf16.bf16.f32 "
                 "{%0,%1,%2,%3}, {%4,%5,%6,%7}, {%8,%9}, {%0,%1,%2,%3};"
                 : "+f"(c[0]), "+f"(c[1]), "+f"(c[2]), "+f"(c[3])
                 : "r"(a0), "r"(a1), "r"(a2), "r"(a3), "r"(b0), "r"(b1));
}
__device__ __forceinline__ uint32_t pack_bf16x2(float lo, float hi) {
    uint32_t r;  // lo lands in low 16 bits
    asm("cvt.rn.bf16x2.f32 %0, %1, %2;" : "=r"(r) : "f"(hi), "f"(lo));
    return r;
}
__device__ __forceinline__ uint32_t lo_pack(uint32_t hi, float w0, float w1) {
    const float h0 = __uint_as_float(hi << 16);
    const float h1 = __uint_as_float(hi & 0xffff0000u);
    return pack_bf16x2(w0 - h0, w1 - h1);
}
__device__ __forceinline__ float wval(float x, int m) {
    const float lr = fmaxf(x, ALPHA * x);
    const float v  = __expf(lr);
    return (m > 0) ? v : 0.f;
}

// ---------------------------------------------------------------------------
// Kernel 1 (fused front, 8 rows/CTA): h = X@W; s1/s2; bf16 hi/lo transpose.
// grid 1024 x 128 threads -> high occupancy, latency hidden.
// ---------------------------------------------------------------------------
__global__ __launch_bounds__(128) void k_front(const float* __restrict__ X,
                                               const float* __restrict__ W,
                                               const float* __restrict__ a1,
                                               const float* __restrict__ a2) {
    __shared__ float Xs[8][INF];
    __shared__ float hs[8][65];
    const int tid = threadIdx.x;
    const int r0  = blockIdx.x * 8;

    // stage X tile [8][256]
    const float4* Xg  = (const float4*)(X + (long)r0 * INF);
    float4*       Xs4 = (float4*)&Xs[0][0];
#pragma unroll
    for (int it = 0; it < 4; it++) Xs4[it * 128 + tid] = Xg[it * 128 + tid];
    __syncthreads();

    const int r = tid >> 4, tc = tid & 15;
    const float4* W4 = (const float4*)W;
    float4 acc = make_float4(0.f, 0.f, 0.f, 0.f);
#pragma unroll 8
    for (int k = 0; k < INF; k++) {
        const float  x = Xs[r][k];
        const float4 w = W4[k * 16 + tc];
        acc.x += x * w.x; acc.y += x * w.y; acc.z += x * w.z; acc.w += x * w.w;
    }

    // s1/s2: per-thread partial over 4 cols, then 16-lane reduction
    {
        const float4 va1 = __ldg(&((const float4*)a1)[tc]);
        const float4 va2 = __ldg(&((const float4*)a2)[tc]);
        float p1 = acc.x * va1.x + acc.y * va1.y + acc.z * va1.z + acc.w * va1.w;
        float p2 = acc.x * va2.x + acc.y * va2.y + acc.z * va2.z + acc.w * va2.w;
#pragma unroll
        for (int o = 8; o; o >>= 1) {
            p1 += __shfl_down_sync(0xffffffffu, p1, o, 16);
            p2 += __shfl_down_sync(0xffffffffu, p2, o, 16);
        }
        if (tc == 0) { g_s1[r0 + r] = p1; g_s2[r0 + r] = p2; }
    }

    // stash h into smem for transpose
    hs[r][tc * 4 + 0] = acc.x; hs[r][tc * 4 + 1] = acc.y;
    hs[r][tc * 4 + 2] = acc.z; hs[r][tc * 4 + 3] = acc.w;
    __syncthreads();

    // transpose + hi/lo split: thread = (c = tid>>1, part = tid&1)
    const int c = tid >> 1, part = tid & 1;
    float v[8];
#pragma unroll
    for (int k = 0; k < 8; k++) v[k] = hs[k][c];
    uint32_t u[4];
#pragma unroll
    for (int p = 0; p < 4; p++) {
        const float f0 = v[2 * p], f1 = v[2 * p + 1];
        const uint32_t hi = pack_bf16x2(f0, f1);
        u[p] = part ? lo_pack(hi, f0, f1) : hi;
    }
    uint4* dst = part ? g_hTlo4 : g_hThi4;
    dst[c * 1024 + (r0 >> 3)] = make_uint4(u[0], u[1], u[2], u[3]);
}

// ---------------------------------------------------------------------------
// Kernel 2: fused masked-exp weight-gen + mma.sync 3xBF16 GEMM, 512 threads.
// Warps 0-7 handle ks 0..1, warps 8-15 handle ks 2..3 (same 128 i-rows);
// partial accumulators merged through smem at the end.
// ---------------------------------------------------------------------------
__device__ __forceinline__ void stage_tile(uint32_t sb, int buf, const int* __restrict__ adj,
                                           int ibase, int j0, int tid) {
    const uint32_t adjB = sb + (buf ? OFF_ADJ1 : OFF_ADJ0);
#pragma unroll
    for (int it = 0; it < 4; it++) {
        const int lin = it * 512 + tid;
        const int ii = lin >> 4, ch = lin & 15;
        cpa16(adjB + ii * ADJ_PITCH + ch * 16,
              adj + (long)(ibase + ii) * NN + j0 + ch * 4);
    }
    const uint32_t hhiB = sb + (buf ? OFF_HHI1 : OFF_HHI0);
    const uint32_t hloB = sb + (buf ? OFF_HLO1 : OFF_HLO0);
    {
        const int n = tid >> 3, ch = tid & 7;
        const uint32_t off = n * 128 + ((ch ^ (n & 7)) << 4);
        cpa16(hhiB + off, g_hThi4 + n * 1024 + (j0 >> 3) + ch);
        cpa16(hloB + off, g_hTlo4 + n * 1024 + (j0 >> 3) + ch);
    }
}

__global__ __launch_bounds__(512, 1) void k_attn(const int* __restrict__ adj) {
    extern __shared__ __align__(128) unsigned char smem[];
    const uint32_t sb = smem_u32(smem);
    const int tid = threadIdx.x, lane = tid & 31, wid = tid >> 5;
    const int half = wid >> 3, w8 = wid & 7;
    const int ibase  = blockIdx.x * BI;
    const int jsplit = blockIdx.y;
    const int jbase  = jsplit * (NN / JSPLIT);

    if (tid < BI) ((float*)smem)[tid] = g_s1[ibase + tid];

    const int g  = lane >> 2;
    const int t2 = (lane & 3) * 2;
    const int p_nloc = ((lane >> 4) << 3) + (lane & 7);
    const int ckb    = (lane >> 3) & 1;

    float acc[8][4];
#pragma unroll
    for (int n = 0; n < 8; n++)
#pragma unroll
        for (int q = 0; q < 4; q++) acc[n][q] = 0.f;
    float z0 = 0.f, z1 = 0.f;

    stage_tile(sb, 0, adj, ibase, jbase, tid);
    asm volatile("cp.async.commit_group;" ::: "memory");

    const int r0loc = w8 * 16 + g;
    const int r1loc = r0loc + 8;

    for (int t = 0; t < NTILES; t++) {
        const int b  = t & 1;
        const int j0 = jbase + t * BJ;

        if (t + 1 < NTILES) {
            stage_tile(sb, b ^ 1, adj, ibase, j0 + BJ, tid);
            asm volatile("cp.async.commit_group;" ::: "memory");
            asm volatile("cp.async.wait_group 1;" ::: "memory");
        } else {
            asm volatile("cp.async.wait_group 0;" ::: "memory");
        }
        __syncthreads();

        const uint32_t adjOff = b ? OFF_ADJ1 : OFF_ADJ0;
        const uint32_t hhiB = sb + (b ? OFF_HHI1 : OFF_HHI0);
        const uint32_t hloB = sb + (b ? OFF_HLO1 : OFF_HLO0);
        const float s1r0 = ((const float*)smem)[r0loc];
        const float s1r1 = ((const float*)smem)[r1loc];

#pragma unroll
        for (int kk = 0; kk < 2; kk++) {
            const int ks = half * 2 + kk;
            const int jk = j0 + ks * 16;

            // ---- B fragments ----
            uint32_t bh[4][4], bl[4][4];
            const int ck = ks * 2 + ckb;
#pragma unroll
            for (int p = 0; p < 4; p++) {
                const int nl = p * 16 + p_nloc;
                const uint32_t off = nl * 128 + ((ck ^ (nl & 7)) << 4);
                ldsm4(bh[p], hhiB + off);
                ldsm4(bl[p], hloB + off);
            }

            // ---- A fragments: masked-exp weights ----
            const unsigned char* aR0 = smem + adjOff + r0loc * ADJ_PITCH + (ks * 16 + t2) * 4;
            const unsigned char* aR1 = smem + adjOff + r1loc * ADJ_PITCH + (ks * 16 + t2) * 4;
            const int2 m00 = *(const int2*)aR0;
            const int2 m01 = *(const int2*)(aR0 + 32);
            const int2 m10 = *(const int2*)aR1;
            const int2 m11 = *(const int2*)(aR1 + 32);
            const float2 sa  = *(const float2*)&g_s2[jk + t2];
            const float2 sb2 = *(const float2*)&g_s2[jk + t2 + 8];

            const float w00 = wval(s1r0 + sa.x,  m00.x), w01 = wval(s1r0 + sa.y,  m00.y);
            const float w02 = wval(s1r0 + sb2.x, m01.x), w03 = wval(s1r0 + sb2.y, m01.y);
            const float w10 = wval(s1r1 + sa.x,  m10.x), w11 = wval(s1r1 + sa.y,  m10.y);
            const float w12 = wval(s1r1 + sb2.x, m11.x), w13 = wval(s1r1 + sb2.y, m11.y);
            z0 += (w00 + w01) + (w02 + w03);
            z1 += (w10 + w11) + (w12 + w13);

            const uint32_t a0h = pack_bf16x2(w00, w01), a1h = pack_bf16x2(w10, w11);
            const uint32_t a2h = pack_bf16x2(w02, w03), a3h = pack_bf16x2(w12, w13);
            const uint32_t a0l = lo_pack(a0h, w00, w01), a1l = lo_pack(a1h, w10, w11);
            const uint32_t a2l = lo_pack(a2h, w02, w03), a3l = lo_pack(a3h, w12, w13);

            // ---- 24 mma, pass-outer ----
#pragma unroll
            for (int p = 0; p < 4; p++)
#pragma unroll
                for (int q = 0; q < 2; q++)
                    mma_bf16(acc[p * 2 + q], a0h, a1h, a2h, a3h,
                             bh[p][q * 2], bh[p][q * 2 + 1]);
#pragma unroll
            for (int p = 0; p < 4; p++)
#pragma unroll
                for (int q = 0; q < 2; q++)
                    mma_bf16(acc[p * 2 + q], a0l, a1l, a2l, a3l,
                             bh[p][q * 2], bh[p][q * 2 + 1]);
#pragma unroll
            for (int p = 0; p < 4; p++)
#pragma unroll
                for (int q = 0; q < 2; q++)
                    mma_bf16(acc[p * 2 + q], a0h, a1h, a2h, a3h,
                             bl[p][q * 2], bl[p][q * 2 + 1]);
        }
        __syncthreads();
    }

    // ---- quad-reduce Z within each half ----
    z0 += __shfl_xor_sync(0xffffffffu, z0, 1);
    z0 += __shfl_xor_sync(0xffffffffu, z0, 2);
    z1 += __shfl_xor_sync(0xffffffffu, z1, 1);
    z1 += __shfl_xor_sync(0xffffffffu, z1, 2);

    // ---- merge halves through smem (aliases dead adj buffers) ----
    float* ab = (float*)(smem + OFF_RED);
    float* zb = (float*)(smem + OFF_ZRED);
    if (half == 1) {
        if ((lane & 3) == 0) { zb[r0loc] = z0; zb[r1loc] = z1; }
        float* dst = ab + (tid - 256) * RED_STRIDE;
#pragma unroll
        for (int nt = 0; nt < 8; nt++)
            *(float4*)(dst + nt * 4) = make_float4(acc[nt][0], acc[nt][1],
                                                   acc[nt][2], acc[nt][3]);
    }
    __syncthreads();
    if (half == 0) {
        const float* src = ab + tid * RED_STRIDE;
#pragma unroll
        for (int nt = 0; nt < 8; nt++) {
            const float4 o = *(const float4*)(src + nt * 4);
            acc[nt][0] += o.x; acc[nt][1] += o.y;
            acc[nt][2] += o.z; acc[nt][3] += o.w;
        }
        if ((lane & 3) == 0) {
            g_z[(long)jsplit * NN + ibase + r0loc] = z0 + zb[r0loc];
            g_z[(long)jsplit * NN + ibase + r1loc] = z1 + zb[r1loc];
        }
        const long obase = (long)jsplit * NN + ibase;
#pragma unroll
        for (int nt = 0; nt < 8; nt++) {
            const int col = nt * 8 + t2;
            *(float2*)&g_acc[(obase + r0loc) * OUTF + col] = make_float2(acc[nt][0], acc[nt][1]);
            *(float2*)&g_acc[(obase + r1loc) * OUTF + col] = make_float2(acc[nt][2], acc[nt][3]);
        }
    }
}

// ---------------------------------------------------------------------------
// Kernel 3: combine splits, normalize, ELU.
// ---------------------------------------------------------------------------
__global__ __launch_bounds__(256) void k_combine(float* __restrict__ out) {
    const int idx = blockIdx.x * 256 + threadIdx.x;
    const int row = idx >> 6;
    float z = 0.f, v = 0.f;
#pragma unroll
    for (int s = 0; s < JSPLIT; s++) {
        z += g_z[(long)s * NN + row];
        v += g_acc[(long)s * NN * OUTF + idx];
    }
    v /= z;
    out[idx] = (v > 0.f) ? v : expm1f(v);
}

// ---------------------------------------------------------------------------
extern "C" void kernel_launch(void* const* d_in, const int* in_sizes, int n_in,
                              void* d_out, int out_size) {
    (void)in_sizes; (void)n_in; (void)out_size;
    const float* X   = (const float*)d_in[0];
    const int*   adj = (const int*)  d_in[1];
    const float* W   = (const float*)d_in[2];
    const float* a1  = (const float*)d_in[3];
    const float* a2  = (const float*)d_in[4];
    float* out = (float*)d_out;

    cudaFuncSetAttribute(k_attn, cudaFuncAttributeMaxDynamicSharedMemorySize, SMEM_ATTN);

    k_front  <<<NN / 8, 128>>>(X, W, a1, a2);
    k_attn   <<<dim3(NN / BI, JSPLIT), 512, SMEM_ATTN>>>(adj);
    k_combine<<<NN * OUTF / 256, 256>>>(out);
}